// round 3
// baseline (speedup 1.0000x reference)
#include <cuda_runtime.h>
#include <math.h>

// Problem constants
#define BB 2
#define SS 2048
#define HH 12
#define DD 768

constexpr long QKV_ELEMS = (long)BB * HH * SS * DD;   // 37,748,736
constexpr long P_ELEMS   = (long)BB * HH * SS * SS;   // 100,663,296
constexpr long CTX_ELEMS = (long)BB * SS * HH * DD;   // 37,748,736
constexpr long OUT_ELEMS = (long)BB * SS * DD;        // 3,145,728
constexpr long FFH_ELEMS = (long)BB * SS * 4 * DD;    // 12,582,912

// Scratch: __device__ globals (no allocation allowed in kernel_launch)
__device__ float g_Q[QKV_ELEMS];
__device__ float g_K[QKV_ELEMS];
__device__ float g_V[QKV_ELEMS];
__device__ float g_P[P_ELEMS];
__device__ float g_ctx[CTX_ELEMS];
__device__ float g_attn[OUT_ELEMS];
__device__ float g_xn[OUT_ELEMS];
__device__ float g_ffh[FFH_ELEMS];

// ---------------------------------------------------------------------------
// Generic 128x128x8 SGEMM, 256 threads, 8x8 accumulators per thread.
//   C[m,n] = sum_k A[m,k] * B(k,n)     (TRANSB=false: B row-major KxN)
//                                      (TRANSB=true : B row-major NxK)
// EPI: 0 = store, 1 = store*scale, 2 = exact GELU, 3 = residual add
// CAUSAL: skip output tiles fully above the diagonal (scores GEMM)
// KLIM: limit K loop to m0+128 (ctx GEMM over causal-zeroed P)
// Batch: grid.z -> (b = z/Hn, h = z%Hn), per-operand strides.
// All M,N multiples of 128; all K multiples of 8. No bounds checks needed.
// ---------------------------------------------------------------------------
template <bool TRANSB, int EPI, bool CAUSAL, bool KLIM>
__global__ __launch_bounds__(256) void gemm_k(
    const float* __restrict__ A, const float* __restrict__ Bm,
    float* __restrict__ C, const float* __restrict__ Res,
    int M, int N, int K, int lda, int ldb, int ldc,
    long sAb, long sAh, long sBb, long sBh, long sCb, long sCh,
    int Hn, float scale)
{
    const int m0 = blockIdx.y * 128;
    const int n0 = blockIdx.x * 128;
    if (CAUSAL && n0 > m0) return;  // tile entirely above the causal diagonal

    const int z  = blockIdx.z;
    const int bb = z / Hn;
    const int hh = z - bb * Hn;
    A  += bb * sAb + hh * sAh;
    Bm += bb * sBb + hh * sBh;
    C  += bb * sCb + hh * sCh;

    const int Keff = KLIM ? min(K, m0 + 128) : K;

    __shared__ float As[8][128];
    __shared__ float Bs[8][128];

    const int tid  = threadIdx.x;
    const int rowA = tid >> 1;         // 0..127
    const int colA = (tid & 1) * 4;    // 0 or 4
    const int rowB = tid >> 5;         // 0..7   (NN)
    const int colB = (tid & 31) * 4;   // 0..124 (NN)
    const int tRow = (tid >> 4) * 8;
    const int tCol = (tid & 15) * 8;

    float acc[8][8];
#pragma unroll
    for (int i = 0; i < 8; i++)
#pragma unroll
        for (int j = 0; j < 8; j++) acc[i][j] = 0.f;

    const float* Aptr = A + (long)(m0 + rowA) * lda + colA;

    for (int k0 = 0; k0 < Keff; k0 += 8) {
        // A tile: 128(m) x 8(k), stored transposed As[k][m]
        float4 av = *reinterpret_cast<const float4*>(Aptr + k0);
        As[colA + 0][rowA] = av.x;
        As[colA + 1][rowA] = av.y;
        As[colA + 2][rowA] = av.z;
        As[colA + 3][rowA] = av.w;

        if (!TRANSB) {
            // B tile: 8(k) x 128(n)
            float4 bv = *reinterpret_cast<const float4*>(
                Bm + (long)(k0 + rowB) * ldb + n0 + colB);
            *reinterpret_cast<float4*>(&Bs[rowB][colB]) = bv;
        } else {
            // B stored NxK: load 128(n) x 8(k), scatter into Bs[k][n]
            float4 bv = *reinterpret_cast<const float4*>(
                Bm + (long)(n0 + rowA) * ldb + k0 + colA);
            Bs[colA + 0][rowA] = bv.x;
            Bs[colA + 1][rowA] = bv.y;
            Bs[colA + 2][rowA] = bv.z;
            Bs[colA + 3][rowA] = bv.w;
        }
        __syncthreads();

#pragma unroll
        for (int kk = 0; kk < 8; kk++) {
            float a[8], b[8];
            *reinterpret_cast<float4*>(&a[0]) =
                *reinterpret_cast<const float4*>(&As[kk][tRow]);
            *reinterpret_cast<float4*>(&a[4]) =
                *reinterpret_cast<const float4*>(&As[kk][tRow + 4]);
            *reinterpret_cast<float4*>(&b[0]) =
                *reinterpret_cast<const float4*>(&Bs[kk][tCol]);
            *reinterpret_cast<float4*>(&b[4]) =
                *reinterpret_cast<const float4*>(&Bs[kk][tCol + 4]);
#pragma unroll
            for (int i = 0; i < 8; i++)
#pragma unroll
                for (int j = 0; j < 8; j++) acc[i][j] += a[i] * b[j];
        }
        __syncthreads();
    }

#pragma unroll
    for (int i = 0; i < 8; i++) {
        const int m = m0 + tRow + i;
#pragma unroll
        for (int j = 0; j < 8; j++) {
            const int n = n0 + tCol + j;
            float v = acc[i][j];
            const long idx = (long)m * ldc + n;
            if (EPI == 1) v *= scale;
            else if (EPI == 2) v = 0.5f * v * (1.f + erff(v * 0.70710678118654752f));
            else if (EPI == 3) v += Res[idx];
            C[idx] = v;
        }
    }
}

// ---------------------------------------------------------------------------
// Row-wise causal softmax, in place on the raw-scores buffer.
// One block per (b,h,q) row; valid length = q+1; zero-fills up to the end of
// the row's 128-aligned block so the ctx GEMM can K-limit at m0+128.
// ---------------------------------------------------------------------------
__global__ __launch_bounds__(256) void softmax_k(float* __restrict__ P)
{
    const long r  = blockIdx.x;          // 0 .. B*H*S-1
    const int  q  = (int)(r % SS);
    float* row    = P + r * (long)SS;
    const int len = q + 1;
    const int t   = threadIdx.x;

    float v[8];
    float mx = -INFINITY;
#pragma unroll
    for (int i = 0; i < 8; i++) {
        const int k = t + i * 256;
        v[i] = (k < len) ? row[k] : -INFINITY;
        mx = fmaxf(mx, v[i]);
    }

    __shared__ float red[256];
    red[t] = mx;
    __syncthreads();
    for (int s = 128; s > 0; s >>= 1) {
        if (t < s) red[t] = fmaxf(red[t], red[t + s]);
        __syncthreads();
    }
    mx = red[0];
    __syncthreads();

    float sum = 0.f;
#pragma unroll
    for (int i = 0; i < 8; i++) {
        const int k = t + i * 256;
        if (k < len) { v[i] = expf(v[i] - mx); sum += v[i]; }
        else v[i] = 0.f;
    }
    red[t] = sum;
    __syncthreads();
    for (int s = 128; s > 0; s >>= 1) {
        if (t < s) red[t] += red[t + s];
        __syncthreads();
    }
    const float inv = 1.f / red[0];

    const int zlen = (q / 128 + 1) * 128;  // zero masked entries within block
#pragma unroll
    for (int i = 0; i < 8; i++) {
        const int k = t + i * 256;
        if (k < zlen) row[k] = v[i] * inv;
    }
}

// ---------------------------------------------------------------------------
// LayerNorm (no affine), one block per row of 768.
// ---------------------------------------------------------------------------
__global__ __launch_bounds__(256) void ln_k(const float* __restrict__ X,
                                            float* __restrict__ Y)
{
    const long r  = blockIdx.x;  // 0 .. B*S-1
    const float* x = X + r * (long)DD;
    float* y       = Y + r * (long)DD;
    const int t    = threadIdx.x;

    float s = 0.f, s2 = 0.f;
#pragma unroll
    for (int i = 0; i < 3; i++) {
        const float v = x[t + i * 256];
        s += v; s2 += v * v;
    }
    __shared__ float rs[256], rs2[256];
    rs[t] = s; rs2[t] = s2;
    __syncthreads();
    for (int st = 128; st > 0; st >>= 1) {
        if (t < st) { rs[t] += rs[t + st]; rs2[t] += rs2[t + st]; }
        __syncthreads();
    }
    const float mu   = rs[0] * (1.f / DD);
    const float var  = rs2[0] * (1.f / DD) - mu * mu;
    const float rstd = rsqrtf(var + 1e-5f);
#pragma unroll
    for (int i = 0; i < 3; i++) {
        const int k = t + i * 256;
        y[k] = (x[k] - mu) * rstd;
    }
}

// ---------------------------------------------------------------------------
extern "C" void kernel_launch(void* const* d_in, const int* in_sizes, int n_in,
                              void* d_out, int out_size)
{
    const float* x  = (const float*)d_in[0];
    const float* Wq = (const float*)d_in[1];
    const float* Wk = (const float*)d_in[2];
    const float* Wv = (const float*)d_in[3];
    const float* Wo = (const float*)d_in[4];
    const float* W1 = (const float*)d_in[5];
    const float* W2 = (const float*)d_in[6];
    float* out = (float*)d_out;

    float *Q, *K, *V, *P, *ctx, *attn, *xn, *ffh;
    cudaGetSymbolAddress((void**)&Q,    g_Q);
    cudaGetSymbolAddress((void**)&K,    g_K);
    cudaGetSymbolAddress((void**)&V,    g_V);
    cudaGetSymbolAddress((void**)&P,    g_P);
    cudaGetSymbolAddress((void**)&ctx,  g_ctx);
    cudaGetSymbolAddress((void**)&attn, g_attn);
    cudaGetSymbolAddress((void**)&xn,   g_xn);
    cudaGetSymbolAddress((void**)&ffh,  g_ffh);

    const dim3 blk(256);
    const long sSD  = (long)SS * DD;          // per-head Q/K/V stride
    const long sBSD = (long)HH * SS * DD;     // per-batch Q/K/V stride

    // 1-3) QKV projections: per (b,h): [S,D] = x[b] @ W[h]   (NN)
    {
        dim3 g(DD / 128, SS / 128, BB * HH);
        gemm_k<false, 0, false, false><<<g, blk>>>(
            x, Wq, Q, nullptr, SS, DD, DD, DD, DD, DD,
            sSD, 0L, 0L, (long)DD * DD, sBSD, sSD, HH, 1.f);
        gemm_k<false, 0, false, false><<<g, blk>>>(
            x, Wk, K, nullptr, SS, DD, DD, DD, DD, DD,
            sSD, 0L, 0L, (long)DD * DD, sBSD, sSD, HH, 1.f);
        gemm_k<false, 0, false, false><<<g, blk>>>(
            x, Wv, V, nullptr, SS, DD, DD, DD, DD, DD,
            sSD, 0L, 0L, (long)DD * DD, sBSD, sSD, HH, 1.f);
    }

    // 4) Raw scores: per (b,h): S_raw = (Q @ K^T) * 1/sqrt(D)   (NT, causal skip)
    {
        dim3 g(SS / 128, SS / 128, BB * HH);
        gemm_k<true, 1, true, false><<<g, blk>>>(
            Q, K, P, nullptr, SS, SS, DD, DD, DD, SS,
            sBSD, sSD, sBSD, sSD, (long)HH * SS * SS, (long)SS * SS, HH,
            rsqrtf((float)DD));
    }

    // 5) Causal softmax, in place
    softmax_k<<<BB * HH * SS, 256>>>(P);

    // 6) ctx = P @ V, scattered into [B,S,H*D]   (NN, K-limited at diagonal)
    {
        dim3 g(DD / 128, SS / 128, BB * HH);
        gemm_k<false, 0, false, true><<<g, blk>>>(
            P, V, ctx, nullptr, SS, DD, SS, SS, DD, HH * DD,
            (long)HH * SS * SS, (long)SS * SS, sBSD, sSD,
            (long)SS * HH * DD, (long)DD, HH, 1.f);
    }

    // 7) attn = ctx @ W_o^T : [4096, 9216] x [768, 9216]^T   (NT)
    {
        dim3 g(DD / 128, (BB * SS) / 128, 1);
        gemm_k<true, 0, false, false><<<g, blk>>>(
            ctx, Wo, attn, nullptr, BB * SS, DD, HH * DD, HH * DD, HH * DD, DD,
            0L, 0L, 0L, 0L, 0L, 0L, 1, 1.f);
    }

    // 8) LayerNorm(attn) -> xn
    ln_k<<<BB * SS, 256>>>(attn, xn);

    // 9) ffh = GELU(xn @ ff_w1^T) : [4096,768] x [3072,768]^T   (NT + GELU)
    {
        dim3 g((4 * DD) / 128, (BB * SS) / 128, 1);
        gemm_k<true, 2, false, false><<<g, blk>>>(
            xn, W1, ffh, nullptr, BB * SS, 4 * DD, DD, DD, DD, 4 * DD,
            0L, 0L, 0L, 0L, 0L, 0L, 1, 1.f);
    }

    // 10) out = attn + ffh @ ff_w2^T : [4096,3072] x [768,3072]^T  (NT + residual)
    {
        dim3 g(DD / 128, (BB * SS) / 128, 1);
        gemm_k<true, 3, false, false><<<g, blk>>>(
            ffh, W2, out, attn, BB * SS, DD, 4 * DD, 4 * DD, 4 * DD, DD,
            0L, 0L, 0L, 0L, 0L, 0L, 1, 1.f);
    }
}

// round 5
// speedup vs baseline: 2.3406x; 2.3406x over previous
#include <cuda_runtime.h>
#include <cuda_bf16.h>
#include <math.h>
#include <stdint.h>

#define BB 2
#define SS 2048
#define HH 12
#define DD 768
#define FF (4*DD)

typedef __nv_bfloat16 bf16;

constexpr long QKV_E = (long)BB*HH*SS*DD;
constexpr long P_E   = (long)BB*HH*SS*SS;
constexpr long CTX_E = (long)BB*SS*HH*DD;
constexpr long OUT_E = (long)BB*SS*DD;
constexpr long FFH_E = (long)BB*SS*FF;
constexpr long WQ_E  = (long)HH*DD*DD;
constexpr long WO_E  = (long)DD*HH*DD;
constexpr long W1_E  = (long)FF*DD;

// ---- scratch (__device__ globals; no allocation allowed) ----
__device__ bf16 g_xh[OUT_E], g_xl[OUT_E];
__device__ bf16 g_WqTh[WQ_E], g_WqTl[WQ_E];
__device__ bf16 g_WkTh[WQ_E], g_WkTl[WQ_E];
__device__ bf16 g_WvTh[WQ_E], g_WvTl[WQ_E];
__device__ bf16 g_Woh[WO_E], g_Wol[WO_E];
__device__ bf16 g_W1h[W1_E], g_W1l[W1_E];
__device__ bf16 g_W2h[W1_E], g_W2l[W1_E];
__device__ bf16 g_Qh[QKV_E], g_Ql[QKV_E];
__device__ bf16 g_Kh[QKV_E], g_Kl[QKV_E];
__device__ float g_V[QKV_E];
__device__ bf16 g_VTh[QKV_E], g_VTl[QKV_E];
__device__ float g_P[P_E];
__device__ bf16 g_Ph[P_E], g_Pl[P_E];
__device__ bf16 g_ch[CTX_E], g_cl[CTX_E];
__device__ float g_attn[OUT_E];
__device__ bf16 g_xnh[OUT_E], g_xnl[OUT_E];
__device__ bf16 g_fh[FFH_E], g_fl[FFH_E];

// ---------------------------------------------------------------------------
__device__ __forceinline__ uint32_t s2u(const void* p){
    uint32_t a;
    asm("{ .reg .u64 t; cvta.to.shared.u64 t, %1; cvt.u32.u64 %0, t; }"
        : "=r"(a) : "l"(p));
    return a;
}
__device__ __forceinline__ void split2(float v, bf16& h, bf16& l){
    h = __float2bfloat16(v);
    l = __float2bfloat16(v - __bfloat162float(h));
}

#define CP_COMMIT() asm volatile("cp.async.commit_group;" ::: "memory")
#define CP_WAIT1()  asm volatile("cp.async.wait_group 1;" ::: "memory")
#define CP_WAIT0()  asm volatile("cp.async.wait_group 0;" ::: "memory")

__device__ __forceinline__ void ldm_x4(uint32_t* r, uint32_t a){
    asm volatile("ldmatrix.sync.aligned.m8n8.x4.shared.b16 {%0,%1,%2,%3}, [%4];"
        : "=r"(r[0]), "=r"(r[1]), "=r"(r[2]), "=r"(r[3]) : "r"(a));
}

#define MMA(d, a, b) \
    asm volatile("mma.sync.aligned.m16n8k16.row.col.f32.bf16.bf16.f32 " \
        "{%0,%1,%2,%3}, {%4,%5,%6,%7}, {%8,%9}, {%0,%1,%2,%3};" \
        : "+f"((d)[0]), "+f"((d)[1]), "+f"((d)[2]), "+f"((d)[3]) \
        : "r"((a)[0]), "r"((a)[1]), "r"((a)[2]), "r"((a)[3]), \
          "r"((b)[0]), "r"((b)[1]))

// SMEM stage layout: Ah @0, Al @10240, Bh @20480, Bl @30720; rows padded to 80B.
#define STAGE_B 40960
#define NSTAGE  3

__device__ __forceinline__ void stage_load(
    char* sbase, const bf16* __restrict__ Ah, const bf16* __restrict__ Al,
    const bf16* __restrict__ Bh, const bf16* __restrict__ Bl,
    int m0, int n0, int k0, int lda, int ldb, int tid)
{
#pragma unroll
    for (int t = 0; t < 8; ++t){
        const int q = tid + t * 256;
        const int tile = q >> 9;
        const int rem  = q & 511;
        const int r    = rem >> 2;
        const int c    = rem & 3;
        const bf16* gp;
        if (tile == 0)      gp = Ah + (long)(m0 + r) * lda + k0 + c * 8;
        else if (tile == 1) gp = Al + (long)(m0 + r) * lda + k0 + c * 8;
        else if (tile == 2) gp = Bh + (long)(n0 + r) * ldb + k0 + c * 8;
        else                gp = Bl + (long)(n0 + r) * ldb + k0 + c * 8;
        const uint32_t so = s2u(sbase + tile * 10240 + r * 80 + c * 16);
        asm volatile("cp.async.cg.shared.global [%0], [%1], 16;" :: "r"(so), "l"(gp));
    }
}

__device__ __forceinline__ void stage_mma(uint32_t su, int wm, int wn, int lane,
                                          float (*acc)[4][4])
{
    const int lr = lane & 7, g = lane >> 3;
    const uint32_t aoff = (uint32_t)((((g & 1) * 8 + lr) * 80) + (g >> 1) * 16);
    const uint32_t boff = (uint32_t)((((g >> 1) * 8 + lr) * 80) + (g & 1) * 16);
    const uint32_t uAh = su + (uint32_t)(wm * 80) + aoff;
    const uint32_t uAl = uAh + 10240;
    const uint32_t uBh = su + 20480 + (uint32_t)(wn * 80) + boff;
    const uint32_t uBl = uBh + 10240;

#pragma unroll
    for (int kk = 0; kk < 2; ++kk){
        uint32_t ah[4][4], al[4][4], bh[2][4], bl[2][4];
#pragma unroll
        for (int mi = 0; mi < 4; ++mi) ldm_x4(ah[mi], uAh + mi * 1280 + kk * 32);
#pragma unroll
        for (int j = 0; j < 2; ++j)    ldm_x4(bh[j], uBh + j * 1280 + kk * 32);
#pragma unroll
        for (int mi = 0; mi < 4; ++mi)
#pragma unroll
            for (int ni = 0; ni < 4; ++ni)
                MMA(acc[mi][ni], ah[mi], &bh[ni >> 1][(ni & 1) * 2]);
#pragma unroll
        for (int j = 0; j < 2; ++j)    ldm_x4(bl[j], uBl + j * 1280 + kk * 32);
#pragma unroll
        for (int mi = 0; mi < 4; ++mi)
#pragma unroll
            for (int ni = 0; ni < 4; ++ni)
                MMA(acc[mi][ni], ah[mi], &bl[ni >> 1][(ni & 1) * 2]);
#pragma unroll
        for (int mi = 0; mi < 4; ++mi) ldm_x4(al[mi], uAl + mi * 1280 + kk * 32);
#pragma unroll
        for (int mi = 0; mi < 4; ++mi)
#pragma unroll
            for (int ni = 0; ni < 4; ++ni)
                MMA(acc[mi][ni], al[mi], &bh[ni >> 1][(ni & 1) * 2]);
    }
}

// ---------------------------------------------------------------------------
// HMMA GEMM: C[M,N] = A[M,K] * B[N,K]^T (both K-major bf16 hi/lo), fp32 acc.
// EPI: 0=f32 store, 1=f32*scale, 2=GELU->hi/lo, 3=+Res->f32, 4=hi/lo split
// ---------------------------------------------------------------------------
template<int EPI, bool CAUSAL, bool KLIM>
__global__ __launch_bounds__(256) void mm_gemm(
    const bf16* __restrict__ Ah, const bf16* __restrict__ Al,
    const bf16* __restrict__ Bh, const bf16* __restrict__ Bl,
    float* __restrict__ C, bf16* __restrict__ Ch, bf16* __restrict__ Cl,
    const float* __restrict__ Res,
    int K, int lda, int ldb, int ldc,
    long sAb, long sAh_, long sBb, long sBh_, long sCb, long sCh_,
    int Hn, float scale)
{
    const int m0 = blockIdx.y * 128;
    const int n0 = blockIdx.x * 128;
    if (CAUSAL && n0 > m0) return;

    const int z = blockIdx.z, b_ = z / Hn, h_ = z - b_ * Hn;
    Ah += b_*sAb + h_*sAh_;  Al += b_*sAb + h_*sAh_;
    Bh += b_*sBb + h_*sBh_;  Bl += b_*sBb + h_*sBh_;
    const long cOff = b_*sCb + h_*sCh_;

    extern __shared__ char sm[];
    const int tid = threadIdx.x, lane = tid & 31, wid = tid >> 5;
    const int wm = (wid >> 2) * 64, wn = (wid & 3) * 32;

    const int Keff = KLIM ? min(K, m0 + 128) : K;
    const int nst  = Keff >> 5;

    float acc[4][4][4];
#pragma unroll
    for (int i = 0; i < 4; ++i)
#pragma unroll
        for (int j = 0; j < 4; ++j)
#pragma unroll
            for (int r = 0; r < 4; ++r) acc[i][j][r] = 0.f;

    stage_load(sm, Ah, Al, Bh, Bl, m0, n0, 0, lda, ldb, tid);
    CP_COMMIT();
    if (nst > 1){
        stage_load(sm + STAGE_B, Ah, Al, Bh, Bl, m0, n0, 32, lda, ldb, tid);
        CP_COMMIT();
    }

    for (int ks = 0; ks < nst; ++ks){
        if (ks < nst - 1) CP_WAIT1(); else CP_WAIT0();
        __syncthreads();
        if (ks + 2 < nst){
            stage_load(sm + ((ks + 2) % NSTAGE) * STAGE_B, Ah, Al, Bh, Bl,
                       m0, n0, (ks + 2) * 32, lda, ldb, tid);
            CP_COMMIT();
        }
        stage_mma(s2u(sm) + (uint32_t)((ks % NSTAGE) * STAGE_B), wm, wn, lane, acc);
        __syncthreads();
    }

    // Epilogue: direct global stores (2 fp32 per thread per fragment row)
    const int rbase = m0 + wm + (lane >> 2);
    const int cbase = n0 + wn + (lane & 3) * 2;
#pragma unroll
    for (int mi = 0; mi < 4; ++mi){
#pragma unroll
        for (int ni = 0; ni < 4; ++ni){
#pragma unroll
            for (int half = 0; half < 2; ++half){
                const long r = rbase + mi * 16 + half * 8;
                const long n = cbase + ni * 8;
                const long o = cOff + r * (long)ldc + n;
                float v0 = acc[mi][ni][half * 2];
                float v1 = acc[mi][ni][half * 2 + 1];
                if (EPI == 0){
                    float2 s; s.x = v0; s.y = v1;
                    *reinterpret_cast<float2*>(C + o) = s;
                } else if (EPI == 1){
                    float2 s; s.x = v0 * scale; s.y = v1 * scale;
                    *reinterpret_cast<float2*>(C + o) = s;
                } else if (EPI == 2){
                    const float g0 = 0.5f * v0 * (1.f + erff(v0 * 0.70710678118654752f));
                    const float g1 = 0.5f * v1 * (1.f + erff(v1 * 0.70710678118654752f));
                    bf16 h0, l0, h1, l1;
                    split2(g0, h0, l0); split2(g1, h1, l1);
                    __nv_bfloat162 hh; hh.x = h0; hh.y = h1;
                    __nv_bfloat162 ll; ll.x = l0; ll.y = l1;
                    *reinterpret_cast<__nv_bfloat162*>(Ch + o) = hh;
                    *reinterpret_cast<__nv_bfloat162*>(Cl + o) = ll;
                } else if (EPI == 3){
                    const float2 rv = *reinterpret_cast<const float2*>(Res + o);
                    float2 s; s.x = v0 + rv.x; s.y = v1 + rv.y;
                    *reinterpret_cast<float2*>(C + o) = s;
                } else {
                    bf16 h0, l0, h1, l1;
                    split2(v0, h0, l0); split2(v1, h1, l1);
                    __nv_bfloat162 hh; hh.x = h0; hh.y = h1;
                    __nv_bfloat162 ll; ll.x = l0; ll.y = l1;
                    *reinterpret_cast<__nv_bfloat162*>(Ch + o) = hh;
                    *reinterpret_cast<__nv_bfloat162*>(Cl + o) = ll;
                }
            }
        }
    }
}

// ---------------------------------------------------------------------------
// fp32 -> bf16 hi/lo split (flat)
// ---------------------------------------------------------------------------
__global__ __launch_bounds__(256) void split_k(const float* __restrict__ X,
                                               bf16* __restrict__ hi,
                                               bf16* __restrict__ lo, long n)
{
    long i  = blockIdx.x * 256L + threadIdx.x;
    long st = (long)gridDim.x * 256L;
    for (; i < n; i += st){
        bf16 h, l; split2(X[i], h, l);
        hi[i] = h; lo[i] = l;
    }
}

// transpose + split: per z, X[R,C] row-major -> out[C,R] hi/lo
__global__ __launch_bounds__(256) void split_t_k(const float* __restrict__ X,
                                                 bf16* __restrict__ hi,
                                                 bf16* __restrict__ lo,
                                                 int R, int C, long sX, long sO)
{
    __shared__ float t[32][33];
    const float* Xz = X + (long)blockIdx.z * sX;
    const int c0 = blockIdx.x * 32, r0 = blockIdx.y * 32;
    const int tx = threadIdx.x & 31, ty = threadIdx.x >> 5;
#pragma unroll
    for (int i = 0; i < 32; i += 8)
        t[ty + i][tx] = Xz[(long)(r0 + ty + i) * C + c0 + tx];
    __syncthreads();
#pragma unroll
    for (int i = 0; i < 32; i += 8){
        const float v = t[tx][ty + i];
        const long o = (long)blockIdx.z * sO + (long)(c0 + ty + i) * R + r0 + tx;
        bf16 h, l; split2(v, h, l);
        hi[o] = h; lo[o] = l;
    }
}

// ---------------------------------------------------------------------------
// Causal softmax: fp32 scores row -> bf16 hi/lo probs (zero-padded to 128)
// ---------------------------------------------------------------------------
__global__ __launch_bounds__(256) void softmax_k(const float* __restrict__ P,
                                                 bf16* __restrict__ Ph,
                                                 bf16* __restrict__ Pl)
{
    const long r  = blockIdx.x;
    const int  q  = (int)(r % SS);
    const float* row = P + r * (long)SS;
    const int len = q + 1;
    const int t   = threadIdx.x;

    float v[8];
    float mx = -INFINITY;
#pragma unroll
    for (int i = 0; i < 8; ++i){
        const int k = t + i * 256;
        v[i] = (k < len) ? row[k] : -INFINITY;
        mx = fmaxf(mx, v[i]);
    }
    __shared__ float red[256];
    red[t] = mx; __syncthreads();
    for (int s = 128; s > 0; s >>= 1){
        if (t < s) red[t] = fmaxf(red[t], red[t + s]);
        __syncthreads();
    }
    mx = red[0]; __syncthreads();

    float sum = 0.f;
#pragma unroll
    for (int i = 0; i < 8; ++i){
        const int k = t + i * 256;
        if (k < len){ v[i] = expf(v[i] - mx); sum += v[i]; }
        else v[i] = 0.f;
    }
    red[t] = sum; __syncthreads();
    for (int s = 128; s > 0; s >>= 1){
        if (t < s) red[t] += red[t + s];
        __syncthreads();
    }
    const float inv = 1.f / red[0];

    const int zlen = (q / 128 + 1) * 128;
    bf16* ph = Ph + r * (long)SS;
    bf16* pl = Pl + r * (long)SS;
#pragma unroll
    for (int i = 0; i < 8; ++i){
        const int k = t + i * 256;
        if (k < zlen){
            bf16 h, l; split2(v[i] * inv, h, l);
            ph[k] = h; pl[k] = l;
        }
    }
}

// LayerNorm (no affine) -> bf16 hi/lo
__global__ __launch_bounds__(256) void ln_k(const float* __restrict__ X,
                                            bf16* __restrict__ Yh,
                                            bf16* __restrict__ Yl)
{
    const long r = blockIdx.x;
    const float* x = X + r * (long)DD;
    const int t = threadIdx.x;

    float s = 0.f, s2 = 0.f;
#pragma unroll
    for (int i = 0; i < 3; ++i){
        const float v = x[t + i * 256];
        s += v; s2 += v * v;
    }
    __shared__ float rs[256], rs2[256];
    rs[t] = s; rs2[t] = s2; __syncthreads();
    for (int st = 128; st > 0; st >>= 1){
        if (t < st){ rs[t] += rs[t + st]; rs2[t] += rs2[t + st]; }
        __syncthreads();
    }
    const float mu   = rs[0] * (1.f / DD);
    const float var  = rs2[0] * (1.f / DD) - mu * mu;
    const float rstd = rsqrtf(var + 1e-5f);
#pragma unroll
    for (int i = 0; i < 3; ++i){
        const int k = t + i * 256;
        bf16 h, l; split2((x[k] - mu) * rstd, h, l);
        Yh[r * (long)DD + k] = h; Yl[r * (long)DD + k] = l;
    }
}

// ---------------------------------------------------------------------------
extern "C" void kernel_launch(void* const* d_in, const int* in_sizes, int n_in,
                              void* d_out, int out_size)
{
    const float* x  = (const float*)d_in[0];
    const float* Wq = (const float*)d_in[1];
    const float* Wk = (const float*)d_in[2];
    const float* Wv = (const float*)d_in[3];
    const float* Wo = (const float*)d_in[4];
    const float* W1 = (const float*)d_in[5];
    const float* W2 = (const float*)d_in[6];
    float* out = (float*)d_out;

    bf16 *xh,*xl,*WqTh,*WqTl,*WkTh,*WkTl,*WvTh,*WvTl,*Woh,*Wol,*W1h,*W1l,*W2h,*W2l;
    bf16 *Qh,*Ql,*Kh,*Kl,*VTh,*VTl,*Ph,*Pl,*ch,*cl,*xnh,*xnl,*fh,*fl;
    float *V,*P,*attn;
    cudaGetSymbolAddress((void**)&xh, g_xh);   cudaGetSymbolAddress((void**)&xl, g_xl);
    cudaGetSymbolAddress((void**)&WqTh, g_WqTh); cudaGetSymbolAddress((void**)&WqTl, g_WqTl);
    cudaGetSymbolAddress((void**)&WkTh, g_WkTh); cudaGetSymbolAddress((void**)&WkTl, g_WkTl);
    cudaGetSymbolAddress((void**)&WvTh, g_WvTh); cudaGetSymbolAddress((void**)&WvTl, g_WvTl);
    cudaGetSymbolAddress((void**)&Woh, g_Woh); cudaGetSymbolAddress((void**)&Wol, g_Wol);
    cudaGetSymbolAddress((void**)&W1h, g_W1h); cudaGetSymbolAddress((void**)&W1l, g_W1l);
    cudaGetSymbolAddress((void**)&W2h, g_W2h); cudaGetSymbolAddress((void**)&W2l, g_W2l);
    cudaGetSymbolAddress((void**)&Qh, g_Qh);   cudaGetSymbolAddress((void**)&Ql, g_Ql);
    cudaGetSymbolAddress((void**)&Kh, g_Kh);   cudaGetSymbolAddress((void**)&Kl, g_Kl);
    cudaGetSymbolAddress((void**)&V, g_V);
    cudaGetSymbolAddress((void**)&VTh, g_VTh); cudaGetSymbolAddress((void**)&VTl, g_VTl);
    cudaGetSymbolAddress((void**)&P, g_P);
    cudaGetSymbolAddress((void**)&Ph, g_Ph);   cudaGetSymbolAddress((void**)&Pl, g_Pl);
    cudaGetSymbolAddress((void**)&ch, g_ch);   cudaGetSymbolAddress((void**)&cl, g_cl);
    cudaGetSymbolAddress((void**)&attn, g_attn);
    cudaGetSymbolAddress((void**)&xnh, g_xnh); cudaGetSymbolAddress((void**)&xnl, g_xnl);
    cudaGetSymbolAddress((void**)&fh, g_fh);   cudaGetSymbolAddress((void**)&fl, g_fl);

    const int SMEMB = NSTAGE * STAGE_B;   // 122880
    cudaFuncSetAttribute(mm_gemm<4,false,false>, cudaFuncAttributeMaxDynamicSharedMemorySize, SMEMB);
    cudaFuncSetAttribute(mm_gemm<0,false,false>, cudaFuncAttributeMaxDynamicSharedMemorySize, SMEMB);
    cudaFuncSetAttribute(mm_gemm<1,true ,false>, cudaFuncAttributeMaxDynamicSharedMemorySize, SMEMB);
    cudaFuncSetAttribute(mm_gemm<4,false,true >, cudaFuncAttributeMaxDynamicSharedMemorySize, SMEMB);
    cudaFuncSetAttribute(mm_gemm<2,false,false>, cudaFuncAttributeMaxDynamicSharedMemorySize, SMEMB);
    cudaFuncSetAttribute(mm_gemm<3,false,false>, cudaFuncAttributeMaxDynamicSharedMemorySize, SMEMB);

    const long sSD  = (long)SS*DD;
    const long sBSD = (long)HH*SS*DD;

    // --- prep: splits / transposed splits ---
    split_k<<<4096, 256>>>(x, xh, xl, OUT_E);
    split_k<<<4096, 256>>>(Wo, Woh, Wol, WO_E);
    split_k<<<4096, 256>>>(W1, W1h, W1l, W1_E);
    split_k<<<4096, 256>>>(W2, W2h, W2l, W1_E);
    {
        dim3 g(DD/32, DD/32, HH);
        split_t_k<<<g, 256>>>(Wq, WqTh, WqTl, DD, DD, (long)DD*DD, (long)DD*DD);
        split_t_k<<<g, 256>>>(Wk, WkTh, WkTl, DD, DD, (long)DD*DD, (long)DD*DD);
        split_t_k<<<g, 256>>>(Wv, WvTh, WvTl, DD, DD, (long)DD*DD, (long)DD*DD);
    }

    // --- Q, K projections (split output), V projection (fp32) ---
    {
        dim3 g(DD/128, SS/128, BB*HH);
        mm_gemm<4,false,false><<<g, 256, SMEMB>>>(
            xh, xl, WqTh, WqTl, nullptr, Qh, Ql, nullptr,
            DD, DD, DD, DD, sSD, 0L, 0L, (long)DD*DD, sBSD, sSD, HH, 1.f);
        mm_gemm<4,false,false><<<g, 256, SMEMB>>>(
            xh, xl, WkTh, WkTl, nullptr, Kh, Kl, nullptr,
            DD, DD, DD, DD, sSD, 0L, 0L, (long)DD*DD, sBSD, sSD, HH, 1.f);
        mm_gemm<0,false,false><<<g, 256, SMEMB>>>(
            xh, xl, WvTh, WvTl, V, nullptr, nullptr, nullptr,
            DD, DD, DD, DD, sSD, 0L, 0L, (long)DD*DD, sBSD, sSD, HH, 1.f);
    }
    // V -> V^T hi/lo (per b,h: [2048,768] -> [768,2048])
    {
        dim3 g(DD/32, SS/32, BB*HH);
        split_t_k<<<g, 256>>>(V, VTh, VTl, SS, DD, sSD, sSD);
    }
    // --- scores = (Q K^T)/sqrt(D), causal tile skip, fp32 out ---
    {
        dim3 g(SS/128, SS/128, BB*HH);
        mm_gemm<1,true,false><<<g, 256, SMEMB>>>(
            Qh, Ql, Kh, Kl, P, nullptr, nullptr, nullptr,
            DD, DD, DD, SS, sBSD, sSD, sBSD, sSD,
            (long)HH*SS*SS, (long)SS*SS, HH, rsqrtf((float)DD));
    }
    // --- softmax -> hi/lo ---
    softmax_k<<<BB*HH*SS, 256>>>(P, Ph, Pl);
    // --- ctx = P V (K-limited), split output scattered to [B,S,H*D] ---
    {
        dim3 g(DD/128, SS/128, BB*HH);
        mm_gemm<4,false,true><<<g, 256, SMEMB>>>(
            Ph, Pl, VTh, VTl, nullptr, ch, cl, nullptr,
            SS, SS, SS, HH*DD,
            (long)HH*SS*SS, (long)SS*SS, (long)HH*DD*SS, (long)DD*SS,
            (long)SS*HH*DD, (long)DD, HH, 1.f);
    }
    // --- attn = ctx @ Wo^T (fp32) ---
    {
        dim3 g(DD/128, (BB*SS)/128, 1);
        mm_gemm<0,false,false><<<g, 256, SMEMB>>>(
            ch, cl, Woh, Wol, attn, nullptr, nullptr, nullptr,
            HH*DD, HH*DD, HH*DD, DD, 0L,0L,0L,0L,0L,0L, 1, 1.f);
    }
    // --- LN -> hi/lo ---
    ln_k<<<BB*SS, 256>>>(attn, xnh, xnl);
    // --- FFN1: GELU(xn @ W1^T) -> hi/lo ---
    {
        dim3 g(FF/128, (BB*SS)/128, 1);
        mm_gemm<2,false,false><<<g, 256, SMEMB>>>(
            xnh, xnl, W1h, W1l, nullptr, fh, fl, nullptr,
            DD, DD, DD, FF, 0L,0L,0L,0L,0L,0L, 1, 1.f);
    }
    // --- FFN2: out = attn + ffh @ W2^T ---
    {
        dim3 g(DD/128, (BB*SS)/128, 1);
        mm_gemm<3,false,false><<<g, 256, SMEMB>>>(
            fh, fl, W2h, W2l, out, nullptr, nullptr, attn,
            FF, FF, FF, DD, 0L,0L,0L,0L,0L,0L, 1, 1.f);
    }
}